// round 9
// baseline (speedup 1.0000x reference)
#include <cuda_runtime.h>
#include <math.h>

#define EPS 1e-8f
#define THREADS 256

typedef unsigned long long ull;

// ---- packed f32x2 helpers (sm_103a FFMA2 path, PTX-only per SASS_QUICKREF) ----
__device__ __forceinline__ ull pack2(float lo, float hi) {
    ull r; asm("mov.b64 %0, {%1, %2};" : "=l"(r) : "f"(lo), "f"(hi)); return r;
}
__device__ __forceinline__ void unpack2(ull v, float& lo, float& hi) {
    asm("mov.b64 {%0, %1}, %2;" : "=f"(lo), "=f"(hi) : "l"(v));
}
__device__ __forceinline__ ull ffma2(ull a, ull b, ull c) {
    ull d; asm("fma.rn.f32x2 %0, %1, %2, %3;" : "=l"(d) : "l"(a), "l"(b), "l"(c)); return d;
}

// One CTA per batch row b.
// Phase 1: kn[16] (normalized k projection) -> smem as duplicated f32x2 pairs.
// Phase 2: stream 4096 encoder rows; each thread handles a row PAIR (s, s+32)
//          with packed FFMA2: acc_d(pair) += Wq[d][h](dup pair) * x(pair).
//          Wq stored h-major in smem as ulonglong2 -> one broadcast LDS.128
//          feeds two FFMA2. Live set ~70 regs (16 packed accs + staging).
// Phase 3: block log-softmax over S, coalesced store.
__global__ __launch_bounds__(THREADS, 3) void attn_cosine_logsoftmax(
    const float* __restrict__ dec,   // [B,32]
    const float* __restrict__ enc,   // [B,S,32]
    const float* __restrict__ Wq,    // [16,32]
    const float* __restrict__ bq,    // [16]
    const float* __restrict__ Wk,    // [16,32]
    const float* __restrict__ bk,    // [16]
    float* __restrict__ out,         // [B,S]
    int S)
{
    __shared__ float      s_att[4096];
    __shared__ ulonglong2 s_Wp2[32 * 8];   // [h][dd]: pairs (Wq[2dd][h],Wq[2dd][h]),(Wq[2dd+1][h],...)
    __shared__ ull        s_bqp[16];       // (bq[d], bq[d])
    __shared__ ull        s_knp[16];       // (kn[d], kn[d])
    __shared__ float      s_kvec[16];
    __shared__ float      s_red[8];
    __shared__ float      s_bcast[2];

    const int b   = blockIdx.x;
    const int tid = threadIdx.x;

    // ---- stage Wq as duplicated pairs, h-major ----
    // entry e = h*16 + d  ->  pair (Wq[d*32+h], Wq[d*32+h])
    {
        ull* wp = reinterpret_cast<ull*>(s_Wp2);
        #pragma unroll
        for (int e = tid; e < 512; e += THREADS) {
            int h = e >> 4, d = e & 15;
            float w = Wq[d * 32 + h];
            wp[e] = pack2(w, w);
        }
    }
    if (tid < 16) {
        float bv = bq[tid];
        s_bqp[tid] = pack2(bv, bv);
        // k projection for this b (one d per thread)
        float kd = bk[tid];
        const float* wr = Wk + tid * 32;
        const float* xr = dec + b * 32;
        #pragma unroll
        for (int h = 0; h < 32; h++) kd = fmaf(wr[h], xr[h], kd);
        s_kvec[tid] = kd;
    }
    __syncthreads();
    if (tid < 16) {
        float ss = 0.f;
        #pragma unroll
        for (int d = 0; d < 16; d++) { float v = s_kvec[d]; ss = fmaf(v, v, ss); }
        float inv = 1.0f / fmaxf(sqrtf(ss), EPS);
        float knd = s_kvec[tid] * inv;
        s_knp[tid] = pack2(knd, knd);
    }
    __syncthreads();

    // ---- main pass: warp w covers rows [64w, 64w+64): lane l does (64w+l, 64w+32+l) ----
    const float4* encb = reinterpret_cast<const float4*>(enc) + (size_t)b * S * 8;
    float maxv = -INFINITY;

    #pragma unroll 1
    for (int s0 = ((tid & ~31) << 1) + (tid & 31); s0 < S; s0 += 2 * THREADS) {
        const float4* r0 = encb + (size_t)s0 * 8;
        const float4* r1 = r0 + 32 * 8;

        ull acc[16];
        #pragma unroll
        for (int d = 0; d < 16; d++) acc[d] = s_bqp[d];

        #pragma unroll
        for (int hh = 0; hh < 8; hh++) {
            float4 va = r0[hh];
            float4 vb = r1[hh];
            float ax[4] = {va.x, va.y, va.z, va.w};
            float bx[4] = {vb.x, vb.y, vb.z, vb.w};
            #pragma unroll
            for (int j = 0; j < 4; j++) {
                ull xp = pack2(ax[j], bx[j]);
                const ulonglong2* wrow = s_Wp2 + (hh * 4 + j) * 8;
                #pragma unroll
                for (int dd = 0; dd < 8; dd++) {
                    ulonglong2 w = wrow[dd];           // broadcast LDS.128 = 2 dup pairs
                    acc[dd * 2]     = ffma2(xp, w.x, acc[dd * 2]);
                    acc[dd * 2 + 1] = ffma2(xp, w.y, acc[dd * 2 + 1]);
                }
            }
        }

        ull ssp = 0ull, dpp = 0ull;   // packed (0.f, 0.f)
        #pragma unroll
        for (int d = 0; d < 16; d++) {
            ssp = ffma2(acc[d], acc[d], ssp);
            dpp = ffma2(acc[d], s_knp[d], dpp);
        }
        float ss0, ss1, dp0, dp1;
        unpack2(ssp, ss0, ss1);
        unpack2(dpp, dp0, dp1);
        float att0 = dp0 / fmaxf(sqrtf(ss0), EPS);
        float att1 = dp1 / fmaxf(sqrtf(ss1), EPS);
        s_att[s0]      = att0;
        s_att[s0 + 32] = att1;
        maxv = fmaxf(maxv, fmaxf(att0, att1));
    }

    // ---- block max reduce ----
    #pragma unroll
    for (int o = 16; o; o >>= 1)
        maxv = fmaxf(maxv, __shfl_xor_sync(0xFFFFFFFFu, maxv, o));
    if ((tid & 31) == 0) s_red[tid >> 5] = maxv;
    __syncthreads();   // also publishes s_att
    if (tid < 32) {
        float m = (tid < (THREADS / 32)) ? s_red[tid] : -INFINITY;
        #pragma unroll
        for (int o = 4; o; o >>= 1)
            m = fmaxf(m, __shfl_xor_sync(0xFFFFFFFFu, m, o));
        if (tid == 0) s_bcast[0] = m;
    }
    __syncthreads();
    const float gmax = s_bcast[0];

    // ---- sum of exp ----
    float lsum = 0.f;
    #pragma unroll 1
    for (int s = tid; s < S; s += THREADS)
        lsum += __expf(s_att[s] - gmax);

    #pragma unroll
    for (int o = 16; o; o >>= 1)
        lsum += __shfl_xor_sync(0xFFFFFFFFu, lsum, o);
    __syncthreads();
    if ((tid & 31) == 0) s_red[tid >> 5] = lsum;
    __syncthreads();
    if (tid < 32) {
        float sm = (tid < (THREADS / 32)) ? s_red[tid] : 0.f;
        #pragma unroll
        for (int o = 4; o; o >>= 1)
            sm += __shfl_xor_sync(0xFFFFFFFFu, sm, o);
        if (tid == 0) s_bcast[1] = sm;
    }
    __syncthreads();
    const float lse = gmax + logf(s_bcast[1]);

    // ---- coalesced output ----
    float* ob = out + (size_t)b * S;
    #pragma unroll 1
    for (int s = tid; s < S; s += THREADS)
        ob[s] = s_att[s] - lse;
}

extern "C" void kernel_launch(void* const* d_in, const int* in_sizes, int n_in,
                              void* d_out, int out_size) {
    const float* dec = (const float*)d_in[0];   // [B,32]
    const float* enc = (const float*)d_in[1];   // [B,S,32]
    const float* Wq  = (const float*)d_in[2];   // [16,32]
    const float* bq  = (const float*)d_in[3];   // [16]
    const float* Wk  = (const float*)d_in[4];   // [16,32]
    const float* bk  = (const float*)d_in[5];   // [16]
    float* out = (float*)d_out;

    const int H = 32;
    const int B = in_sizes[0] / H;                 // 512
    const int S = in_sizes[1] / (B * H);           // 4096

    attn_cosine_logsoftmax<<<B, THREADS>>>(dec, enc, Wq, bq, Wk, bk, out, S);
}

// round 10
// speedup vs baseline: 8.4714x; 8.4714x over previous
#include <cuda_runtime.h>
#include <math.h>
#include <stdint.h>

#define EPS     1e-8f
#define THREADS 256
#define TILE    256      // rows per smem tile
#define XSTRIDE 33       // floats per row in smem (conflict-free scalar reads)

typedef unsigned long long ull;

// ---- packed f32x2 helpers (sm_103a FFMA2, PTX-only) ----
__device__ __forceinline__ ull pack2(float lo, float hi) {
    ull r; asm("mov.b64 %0, {%1, %2};" : "=l"(r) : "f"(lo), "f"(hi)); return r;
}
__device__ __forceinline__ void unpack2(ull v, float& lo, float& hi) {
    asm("mov.b64 {%0, %1}, %2;" : "=f"(lo), "=f"(hi) : "l"(v));
}
__device__ __forceinline__ ull ffma2(ull a, ull b, ull c) {
    ull d; asm("fma.rn.f32x2 %0, %1, %2, %3;" : "=l"(d) : "l"(a), "l"(b), "l"(c)); return d;
}
// volatile W loads: compiler must NOT hoist/CSE these across the tile loop
__device__ __forceinline__ void lds_w2(uint32_t addr, ull& a, ull& b) {
    asm volatile("ld.shared.v2.u64 {%0, %1}, [%2];" : "=l"(a), "=l"(b) : "r"(addr));
}

// One CTA per batch row b. 4 CTAs/SM -> 592 slots > 512 CTAs = single wave.
// Phase A: kn / W d-pairs setup.
// Phase B: 16 tiles of 256 rows: coalesced float4 gmem->smem stage, then each
//          thread computes one row with d-packed FFMA2 (8 pair-accumulators),
//          att written straight to out[] (gmem, coalesced).
// Phase C: block max, sum-exp over out[] (L2-hot), subtract lse in place.
__global__ __launch_bounds__(THREADS, 4) void attn_cosine_logsoftmax(
    const float* __restrict__ dec,   // [B,32]
    const float* __restrict__ enc,   // [B,S,32]
    const float* __restrict__ Wq,    // [16,32]
    const float* __restrict__ bq,    // [16]
    const float* __restrict__ Wk,    // [16,32]
    const float* __restrict__ bk,    // [16]
    float* __restrict__ out,         // [B,S]
    int S)
{
    __shared__ float s_x[TILE * XSTRIDE];            // 33792 B
    __shared__ __align__(16) ull s_W[32 * 8];        // [h][dd] -> (Wq[2dd][h], Wq[2dd+1][h])
    __shared__ ull   s_bqp[8];                       // (bq[2dd], bq[2dd+1])
    __shared__ ull   s_knp[8];                       // (kn[2dd], kn[2dd+1])
    __shared__ float s_kvec[16];
    __shared__ float s_red[8];
    __shared__ float s_bcast[2];

    const int b   = blockIdx.x;
    const int tid = threadIdx.x;

    // ---- setup: W d-pairs, bq pairs, k projection ----
    for (int e = tid; e < 256; e += THREADS) {
        int h = e >> 3, dd = e & 7;
        s_W[h * 8 + dd] = pack2(Wq[(2 * dd) * 32 + h], Wq[(2 * dd + 1) * 32 + h]);
    }
    if (tid < 8) s_bqp[tid] = pack2(bq[2 * tid], bq[2 * tid + 1]);
    if (tid < 16) {
        float kd = bk[tid];
        const float* wr = Wk + tid * 32;
        const float* xr = dec + b * 32;
        #pragma unroll
        for (int h = 0; h < 32; h++) kd = fmaf(wr[h], xr[h], kd);
        s_kvec[tid] = kd;
    }
    __syncthreads();
    if (tid < 8) {
        float ss = 0.f;
        #pragma unroll
        for (int d = 0; d < 16; d++) { float v = s_kvec[d]; ss = fmaf(v, v, ss); }
        float inv = 1.0f / fmaxf(sqrtf(ss), EPS);
        s_knp[tid] = pack2(s_kvec[2 * tid] * inv, s_kvec[2 * tid + 1] * inv);
    }
    // visibility of s_knp/s_W/s_bqp covered by the first in-loop __syncthreads

    const float4* encb4 = reinterpret_cast<const float4*>(enc) + (size_t)b * S * 8;
    float* att_out = out + (size_t)b * S;
    const uint32_t wbase = (uint32_t)__cvta_generic_to_shared(s_W);
    float maxv = -INFINITY;

    // ---- main tiles ----
    #pragma unroll 1
    for (int base = 0; base < S; base += TILE) {
        // stage: 2048 float4, 8 per thread, warp-contiguous gmem reads
        #pragma unroll
        for (int k = 0; k < (TILE * 8) / THREADS; k++) {
            int L = tid + k * THREADS;
            int idx = base * 8 + L;
            if (idx < S * 8) {
                float4 v = encb4[idx];
                int row = L >> 3, hh = L & 7;
                float* dst = s_x + row * XSTRIDE + hh * 4;
                dst[0] = v.x; dst[1] = v.y; dst[2] = v.z; dst[3] = v.w;
            }
        }
        __syncthreads();

        // compute: one row per thread
        if (base + tid < S) {
            const float* xr = s_x + tid * XSTRIDE;
            ull acc[8];
            #pragma unroll
            for (int j = 0; j < 8; j++) acc[j] = s_bqp[j];

            #pragma unroll 8
            for (int h = 0; h < 32; h++) {
                float xv = xr[h];            // bank (tid+h)%32: conflict-free
                ull xp = pack2(xv, xv);
                uint32_t wa = wbase + (uint32_t)h * 64;
                ull w0, w1, w2, w3, w4, w5, w6, w7;
                lds_w2(wa,      w0, w1);     // broadcast LDS.128
                lds_w2(wa + 16, w2, w3);
                lds_w2(wa + 32, w4, w5);
                lds_w2(wa + 48, w6, w7);
                acc[0] = ffma2(xp, w0, acc[0]);
                acc[1] = ffma2(xp, w1, acc[1]);
                acc[2] = ffma2(xp, w2, acc[2]);
                acc[3] = ffma2(xp, w3, acc[3]);
                acc[4] = ffma2(xp, w4, acc[4]);
                acc[5] = ffma2(xp, w5, acc[5]);
                acc[6] = ffma2(xp, w6, acc[6]);
                acc[7] = ffma2(xp, w7, acc[7]);
            }

            ull ssp = 0ull, dpp = 0ull;      // packed (0.f, 0.f)
            #pragma unroll
            for (int j = 0; j < 8; j++) {
                ssp = ffma2(acc[j], acc[j], ssp);
                dpp = ffma2(acc[j], s_knp[j], dpp);
            }
            float ss0, ss1, dp0, dp1;
            unpack2(ssp, ss0, ss1);
            unpack2(dpp, dp0, dp1);
            float att = (dp0 + dp1) / fmaxf(sqrtf(ss0 + ss1), EPS);
            att_out[base + tid] = att;       // coalesced store
            maxv = fmaxf(maxv, att);
        }
        __syncthreads();
    }

    // ---- block max reduce ----
    #pragma unroll
    for (int o = 16; o; o >>= 1)
        maxv = fmaxf(maxv, __shfl_xor_sync(0xFFFFFFFFu, maxv, o));
    if ((tid & 31) == 0) s_red[tid >> 5] = maxv;
    __syncthreads();
    if (tid < 32) {
        float m = (tid < (THREADS / 32)) ? s_red[tid] : -INFINITY;
        #pragma unroll
        for (int o = 4; o; o >>= 1)
            m = fmaxf(m, __shfl_xor_sync(0xFFFFFFFFu, m, o));
        if (tid == 0) s_bcast[0] = m;
    }
    __syncthreads();
    const float gmax = s_bcast[0];

    // ---- sum of exp (att re-read from out: L2-hot, coalesced) ----
    float lsum = 0.f;
    #pragma unroll 1
    for (int s = tid; s < S; s += THREADS)
        lsum += __expf(att_out[s] - gmax);

    #pragma unroll
    for (int o = 16; o; o >>= 1)
        lsum += __shfl_xor_sync(0xFFFFFFFFu, lsum, o);
    __syncthreads();
    if ((tid & 31) == 0) s_red[tid >> 5] = lsum;
    __syncthreads();
    if (tid < 32) {
        float sm = (tid < (THREADS / 32)) ? s_red[tid] : 0.f;
        #pragma unroll
        for (int o = 4; o; o >>= 1)
            sm += __shfl_xor_sync(0xFFFFFFFFu, sm, o);
        if (tid == 0) s_bcast[1] = sm;
    }
    __syncthreads();
    const float lse = gmax + logf(s_bcast[1]);

    // ---- finalize in place ----
    #pragma unroll 1
    for (int s = tid; s < S; s += THREADS)
        att_out[s] = att_out[s] - lse;
}

extern "C" void kernel_launch(void* const* d_in, const int* in_sizes, int n_in,
                              void* d_out, int out_size) {
    const float* dec = (const float*)d_in[0];   // [B,32]
    const float* enc = (const float*)d_in[1];   // [B,S,32]
    const float* Wq  = (const float*)d_in[2];   // [16,32]
    const float* bq  = (const float*)d_in[3];   // [16]
    const float* Wk  = (const float*)d_in[4];   // [16,32]
    const float* bk  = (const float*)d_in[5];   // [16]
    float* out = (float*)d_out;

    const int H = 32;
    const int B = in_sizes[0] / H;                 // 512
    const int S = in_sizes[1] / (B * H);           // 4096

    attn_cosine_logsoftmax<<<B, THREADS>>>(dec, enc, Wq, bq, Wk, bk, out, S);
}

// round 11
// speedup vs baseline: 9.2022x; 1.0863x over previous
#include <cuda_runtime.h>
#include <math.h>
#include <stdint.h>

#define EPS     1e-8f
#define THREADS 128
#define TILE    256      // rows per smem tile (2 rows per thread)
#define XSTRIDE 33       // floats per row in smem (conflict-free scalar access)

typedef unsigned long long ull;

// ---- packed f32x2 helpers (sm_103a FFMA2, PTX-only) ----
__device__ __forceinline__ ull pack2(float lo, float hi) {
    ull r; asm("mov.b64 %0, {%1, %2};" : "=l"(r) : "f"(lo), "f"(hi)); return r;
}
__device__ __forceinline__ void unpack2(ull v, float& lo, float& hi) {
    asm("mov.b64 {%0, %1}, %2;" : "=f"(lo), "=f"(hi) : "l"(v));
}
__device__ __forceinline__ ull ffma2(ull a, ull b, ull c) {
    ull d; asm("fma.rn.f32x2 %0, %1, %2, %3;" : "=l"(d) : "l"(a), "l"(b), "l"(c)); return d;
}
// volatile W loads: prevent hoisting W into registers across the tile loop
__device__ __forceinline__ void lds_w2(uint32_t addr, ull& a, ull& b) {
    asm volatile("ld.shared.v2.u64 {%0, %1}, [%2];" : "=l"(a), "=l"(b) : "r"(addr));
}

// Dynamic smem layout (bytes):
//   s_x    : TILE*XSTRIDE floats   = 33792
//   s_att  : 4096 floats           = 16384
//   s_W    : 256 ull (16B aligned) =  2048   [h][dd] -> (Wq[2dd][h], Wq[2dd+1][h])
//   s_bqp  : 8 ull
//   s_knp  : 8 ull
//   s_kvec : 16 f, s_red : 4 f, s_bcast : 2 f
#define SMEM_BYTES (TILE * XSTRIDE * 4 + 4096 * 4 + 256 * 8 + 8 * 8 + 8 * 8 + 24 * 4)

__global__ __launch_bounds__(THREADS, 4) void attn_cosine_logsoftmax(
    const float* __restrict__ dec,   // [B,32]
    const float* __restrict__ enc,   // [B,S,32]
    const float* __restrict__ Wq,    // [16,32]
    const float* __restrict__ bq,    // [16]
    const float* __restrict__ Wk,    // [16,32]
    const float* __restrict__ bk,    // [16]
    float* __restrict__ out,         // [B,S]
    int S)
{
    extern __shared__ float smem[];
    float* s_x     = smem;                                   // 8448 floats
    float* s_att   = smem + TILE * XSTRIDE;                  // 4096 floats
    ull*   s_W     = (ull*)(s_att + 4096);                   // 256 (16B aligned)
    ull*   s_bqp   = s_W + 256;
    ull*   s_knp   = s_bqp + 8;
    float* s_kvec  = (float*)(s_knp + 8);
    float* s_red   = s_kvec + 16;
    float* s_bcast = s_red + 4;

    const int b   = blockIdx.x;
    const int tid = threadIdx.x;

    // ---- setup: W d-pairs (h-major), bq pairs, k projection ----
    #pragma unroll
    for (int e = tid; e < 256; e += THREADS) {
        int h = e >> 3, dd = e & 7;
        s_W[h * 8 + dd] = pack2(Wq[(2 * dd) * 32 + h], Wq[(2 * dd + 1) * 32 + h]);
    }
    if (tid < 8) s_bqp[tid] = pack2(bq[2 * tid], bq[2 * tid + 1]);
    if (tid < 16) {
        float kd = bk[tid];
        const float* wr = Wk + tid * 32;
        const float* xr = dec + b * 32;
        #pragma unroll
        for (int h = 0; h < 32; h++) kd = fmaf(wr[h], xr[h], kd);
        s_kvec[tid] = kd;
    }
    __syncthreads();
    if (tid < 8) {
        float ss = 0.f;
        #pragma unroll
        for (int d = 0; d < 16; d++) { float v = s_kvec[d]; ss = fmaf(v, v, ss); }
        float inv = 1.0f / fmaxf(sqrtf(ss), EPS);
        s_knp[tid] = pack2(s_kvec[2 * tid] * inv, s_kvec[2 * tid + 1] * inv);
    }
    // s_knp visibility: covered by the first in-loop __syncthreads below

    const float4* encb4 = reinterpret_cast<const float4*>(enc) + (size_t)b * S * 8;
    const uint32_t wbase = (uint32_t)__cvta_generic_to_shared(s_W);
    float maxv = -INFINITY;

    // ---- main tiles: 16 x (stage 256 rows, compute 2 rows/thread) ----
    #pragma unroll 1
    for (int base = 0; base < S; base += TILE) {
        // stage: 2048 float4, 16 per thread, coalesced LDG.128 + conflict-free
        // SCALAR stores (bank = row + 4*hh + j covers 0..31 exactly per warp)
        #pragma unroll
        for (int k = 0; k < (TILE * 8) / THREADS; k++) {
            int L = tid + k * THREADS;
            float4 v = encb4[base * 8 + L];
            int row = L >> 3, hh = L & 7;
            float* dst = s_x + row * XSTRIDE + hh * 4;
            dst[0] = v.x; dst[1] = v.y; dst[2] = v.z; dst[3] = v.w;
        }
        __syncthreads();

        // compute: rows (base+tid) and (base+tid+128) share each W load
        {
            const float* xr0 = s_x + tid * XSTRIDE;
            const float* xr1 = s_x + (tid + 128) * XSTRIDE;
            ull acc0[8], acc1[8];
            #pragma unroll
            for (int j = 0; j < 8; j++) { acc0[j] = s_bqp[j]; acc1[j] = s_bqp[j]; }

            #pragma unroll 4
            for (int h = 0; h < 32; h++) {
                float xv0 = xr0[h];          // bank (tid+h)%32: conflict-free
                float xv1 = xr1[h];          // (tid+128+h)%32: conflict-free
                ull xp0 = pack2(xv0, xv0);
                ull xp1 = pack2(xv1, xv1);
                uint32_t wa = wbase + (uint32_t)h * 64;
                ull w0, w1, w2, w3, w4, w5, w6, w7;
                lds_w2(wa,      w0, w1);     // broadcast LDS.128
                lds_w2(wa + 16, w2, w3);
                lds_w2(wa + 32, w4, w5);
                lds_w2(wa + 48, w6, w7);
                acc0[0] = ffma2(xp0, w0, acc0[0]);  acc1[0] = ffma2(xp1, w0, acc1[0]);
                acc0[1] = ffma2(xp0, w1, acc0[1]);  acc1[1] = ffma2(xp1, w1, acc1[1]);
                acc0[2] = ffma2(xp0, w2, acc0[2]);  acc1[2] = ffma2(xp1, w2, acc1[2]);
                acc0[3] = ffma2(xp0, w3, acc0[3]);  acc1[3] = ffma2(xp1, w3, acc1[3]);
                acc0[4] = ffma2(xp0, w4, acc0[4]);  acc1[4] = ffma2(xp1, w4, acc1[4]);
                acc0[5] = ffma2(xp0, w5, acc0[5]);  acc1[5] = ffma2(xp1, w5, acc1[5]);
                acc0[6] = ffma2(xp0, w6, acc0[6]);  acc1[6] = ffma2(xp1, w6, acc1[6]);
                acc0[7] = ffma2(xp0, w7, acc0[7]);  acc1[7] = ffma2(xp1, w7, acc1[7]);
            }

            ull ssp0 = 0ull, dpp0 = 0ull, ssp1 = 0ull, dpp1 = 0ull;
            #pragma unroll
            for (int j = 0; j < 8; j++) {
                ull knj = s_knp[j];
                ssp0 = ffma2(acc0[j], acc0[j], ssp0);
                dpp0 = ffma2(acc0[j], knj,    dpp0);
                ssp1 = ffma2(acc1[j], acc1[j], ssp1);
                dpp1 = ffma2(acc1[j], knj,    dpp1);
            }
            float sa, sb, da, db;
            unpack2(ssp0, sa, sb); unpack2(dpp0, da, db);
            float att0 = (da + db) / fmaxf(sqrtf(sa + sb), EPS);
            unpack2(ssp1, sa, sb); unpack2(dpp1, da, db);
            float att1 = (da + db) / fmaxf(sqrtf(sa + sb), EPS);
            s_att[base + tid]       = att0;
            s_att[base + tid + 128] = att1;
            maxv = fmaxf(maxv, fmaxf(att0, att1));
        }
        __syncthreads();
    }

    // ---- block max reduce (4 warps) ----
    #pragma unroll
    for (int o = 16; o; o >>= 1)
        maxv = fmaxf(maxv, __shfl_xor_sync(0xFFFFFFFFu, maxv, o));
    if ((tid & 31) == 0) s_red[tid >> 5] = maxv;
    __syncthreads();
    if (tid < 32) {
        float m = (tid < (THREADS / 32)) ? s_red[tid] : -INFINITY;
        #pragma unroll
        for (int o = 2; o; o >>= 1)
            m = fmaxf(m, __shfl_xor_sync(0xFFFFFFFFu, m, o));
        if (tid == 0) s_bcast[0] = m;
    }
    __syncthreads();
    const float gmax = s_bcast[0];

    // ---- sum of exp over smem att ----
    float lsum = 0.f;
    #pragma unroll 1
    for (int s = tid; s < S; s += THREADS)
        lsum += __expf(s_att[s] - gmax);

    #pragma unroll
    for (int o = 16; o; o >>= 1)
        lsum += __shfl_xor_sync(0xFFFFFFFFu, lsum, o);
    __syncthreads();
    if ((tid & 31) == 0) s_red[tid >> 5] = lsum;
    __syncthreads();
    if (tid < 32) {
        float sm = (tid < (THREADS / 32)) ? s_red[tid] : 0.f;
        #pragma unroll
        for (int o = 2; o; o >>= 1)
            sm += __shfl_xor_sync(0xFFFFFFFFu, sm, o);
        if (tid == 0) s_bcast[1] = sm;
    }
    __syncthreads();
    const float lse = gmax + logf(s_bcast[1]);

    // ---- single coalesced output pass ----
    float* ob = out + (size_t)b * S;
    #pragma unroll 1
    for (int s = tid; s < S; s += THREADS)
        ob[s] = s_att[s] - lse;
}

extern "C" void kernel_launch(void* const* d_in, const int* in_sizes, int n_in,
                              void* d_out, int out_size) {
    const float* dec = (const float*)d_in[0];   // [B,32]
    const float* enc = (const float*)d_in[1];   // [B,S,32]
    const float* Wq  = (const float*)d_in[2];   // [16,32]
    const float* bq  = (const float*)d_in[3];   // [16]
    const float* Wk  = (const float*)d_in[4];   // [16,32]
    const float* bk  = (const float*)d_in[5];   // [16]
    float* out = (float*)d_out;

    const int H = 32;
    const int B = in_sizes[0] / H;                 // 512
    const int S = in_sizes[1] / (B * H);           // 4096

    cudaFuncSetAttribute(attn_cosine_logsoftmax,
                         cudaFuncAttributeMaxDynamicSharedMemorySize, SMEM_BYTES);
    attn_cosine_logsoftmax<<<B, THREADS, SMEM_BYTES>>>(dec, enc, Wq, bq, Wk, bk, out, S);
}

// round 12
// speedup vs baseline: 12.1366x; 1.3189x over previous
#include <cuda_runtime.h>
#include <math.h>
#include <stdint.h>

#define EPS      1e-8f
#define THREADS  128
#define TILE     256     // rows per smem tile (2 rows per thread)
#define NC       4       // chunks per batch row
#define CHUNK    1024    // rows per CTA (S / NC)
#define XSTRIDE  33      // floats per row in smem (conflict-free scalar access)

typedef unsigned long long ull;

// chunk partial exp-sums: partial[b*NC + c] = sum_{s in chunk} exp(att-1)
__device__ float g_partial[512 * NC];

// ---- packed f32x2 helpers (sm_103a FFMA2, PTX-only) ----
__device__ __forceinline__ ull pack2(float lo, float hi) {
    ull r; asm("mov.b64 %0, {%1, %2};" : "=l"(r) : "f"(lo), "f"(hi)); return r;
}
__device__ __forceinline__ void unpack2(ull v, float& lo, float& hi) {
    asm("mov.b64 {%0, %1}, %2;" : "=f"(lo), "=f"(hi) : "l"(v));
}
__device__ __forceinline__ ull ffma2(ull a, ull b, ull c) {
    ull d; asm("fma.rn.f32x2 %0, %1, %2, %3;" : "=l"(d) : "l"(a), "l"(b), "l"(c)); return d;
}
// volatile W loads: prevent hoisting W into registers across the tile loop
__device__ __forceinline__ void lds_w2(uint32_t addr, ull& a, ull& b) {
    asm volatile("ld.shared.v2.u64 {%0, %1}, [%2];" : "=l"(a), "=l"(b) : "r"(addr));
}

// smem: s_x (TILE*XSTRIDE f) + s_W (256 ull) + s_bqp/s_knp (8+8 ull) + misc
#define SMEM_BYTES (TILE * XSTRIDE * 4 + 256 * 8 + 16 * 8 + 24 * 4)

// Kernel 1: CTA (b, c) computes att for rows [c*CHUNK, (c+1)*CHUNK), writes
// att straight to out, accumulates sum(exp(att - 1)) -> g_partial[b*NC+c].
// att <= 1 always (cosine similarity), so shift c=1 replaces the max pass.
__global__ __launch_bounds__(THREADS, 5) void attn_cosine_pass1(
    const float* __restrict__ dec,   // [B,32]
    const float* __restrict__ enc,   // [B,S,32]
    const float* __restrict__ Wq,    // [16,32]
    const float* __restrict__ bq,    // [16]
    const float* __restrict__ Wk,    // [16,32]
    const float* __restrict__ bk,    // [16]
    float* __restrict__ out,         // [B,S]
    int S)
{
    extern __shared__ float smem[];
    float* s_x     = smem;                          // TILE*XSTRIDE floats
    ull*   s_W     = (ull*)(smem + TILE * XSTRIDE); // 256, 16B aligned
    ull*   s_bqp   = s_W + 256;
    ull*   s_knp   = s_bqp + 8;
    float* s_kvec  = (float*)(s_knp + 8);
    float* s_red   = s_kvec + 16;

    const int b   = blockIdx.x >> 2;      // NC = 4
    const int c   = blockIdx.x & (NC - 1);
    const int tid = threadIdx.x;

    // ---- setup: W d-pairs (h-major), bq pairs, k projection ----
    #pragma unroll
    for (int e = tid; e < 256; e += THREADS) {
        int h = e >> 3, dd = e & 7;
        s_W[h * 8 + dd] = pack2(Wq[(2 * dd) * 32 + h], Wq[(2 * dd + 1) * 32 + h]);
    }
    if (tid < 8) s_bqp[tid] = pack2(bq[2 * tid], bq[2 * tid + 1]);
    if (tid < 16) {
        float kd = bk[tid];
        const float* wr = Wk + tid * 32;
        const float* xr = dec + b * 32;
        #pragma unroll
        for (int h = 0; h < 32; h++) kd = fmaf(wr[h], xr[h], kd);
        s_kvec[tid] = kd;
    }
    __syncthreads();
    if (tid < 8) {
        float ss = 0.f;
        #pragma unroll
        for (int d = 0; d < 16; d++) { float v = s_kvec[d]; ss = fmaf(v, v, ss); }
        float inv = 1.0f / fmaxf(sqrtf(ss), EPS);
        s_knp[tid] = pack2(s_kvec[2 * tid] * inv, s_kvec[2 * tid + 1] * inv);
    }
    // s_knp visibility covered by first in-loop __syncthreads

    const int row0 = c * CHUNK;
    const float4* encb4 = reinterpret_cast<const float4*>(enc)
                        + (size_t)b * S * 8 + (size_t)row0 * 8;
    float* ob = out + (size_t)b * S + row0;
    const uint32_t wbase = (uint32_t)__cvta_generic_to_shared(s_W);
    float lsum = 0.f;

    // ---- 4 tiles of 256 rows ----
    #pragma unroll 1
    for (int base = 0; base < CHUNK; base += TILE) {
        // stage: 2048 float4, 16/thread, coalesced LDG.128, conflict-free scalar STS
        #pragma unroll
        for (int k = 0; k < (TILE * 8) / THREADS; k++) {
            int L = tid + k * THREADS;
            float4 v = encb4[base * 8 + L];
            int row = L >> 3, hh = L & 7;
            float* dst = s_x + row * XSTRIDE + hh * 4;
            dst[0] = v.x; dst[1] = v.y; dst[2] = v.z; dst[3] = v.w;
        }
        __syncthreads();

        // compute: rows (tid) and (tid+128) share every W load
        {
            const float* xr0 = s_x + tid * XSTRIDE;
            const float* xr1 = s_x + (tid + 128) * XSTRIDE;
            ull acc0[8], acc1[8];
            #pragma unroll
            for (int j = 0; j < 8; j++) { acc0[j] = s_bqp[j]; acc1[j] = s_bqp[j]; }

            #pragma unroll 4
            for (int h = 0; h < 32; h++) {
                float xv0 = xr0[h];          // bank (tid+h)%32: conflict-free
                float xv1 = xr1[h];
                ull xp0 = pack2(xv0, xv0);
                ull xp1 = pack2(xv1, xv1);
                uint32_t wa = wbase + (uint32_t)h * 64;
                ull w0, w1, w2, w3, w4, w5, w6, w7;
                lds_w2(wa,      w0, w1);     // broadcast LDS.128
                lds_w2(wa + 16, w2, w3);
                lds_w2(wa + 32, w4, w5);
                lds_w2(wa + 48, w6, w7);
                acc0[0] = ffma2(xp0, w0, acc0[0]);  acc1[0] = ffma2(xp1, w0, acc1[0]);
                acc0[1] = ffma2(xp0, w1, acc0[1]);  acc1[1] = ffma2(xp1, w1, acc1[1]);
                acc0[2] = ffma2(xp0, w2, acc0[2]);  acc1[2] = ffma2(xp1, w2, acc1[2]);
                acc0[3] = ffma2(xp0, w3, acc0[3]);  acc1[3] = ffma2(xp1, w3, acc1[3]);
                acc0[4] = ffma2(xp0, w4, acc0[4]);  acc1[4] = ffma2(xp1, w4, acc1[4]);
                acc0[5] = ffma2(xp0, w5, acc0[5]);  acc1[5] = ffma2(xp1, w5, acc1[5]);
                acc0[6] = ffma2(xp0, w6, acc0[6]);  acc1[6] = ffma2(xp1, w6, acc1[6]);
                acc0[7] = ffma2(xp0, w7, acc0[7]);  acc1[7] = ffma2(xp1, w7, acc1[7]);
            }

            ull ssp0 = 0ull, dpp0 = 0ull, ssp1 = 0ull, dpp1 = 0ull;
            #pragma unroll
            for (int j = 0; j < 8; j++) {
                ull knj = s_knp[j];
                ssp0 = ffma2(acc0[j], acc0[j], ssp0);
                dpp0 = ffma2(acc0[j], knj,    dpp0);
                ssp1 = ffma2(acc1[j], acc1[j], ssp1);
                dpp1 = ffma2(acc1[j], knj,    dpp1);
            }
            float sa, sb, da, db;
            unpack2(ssp0, sa, sb); unpack2(dpp0, da, db);
            float att0 = (da + db) / fmaxf(sqrtf(sa + sb), EPS);
            unpack2(ssp1, sa, sb); unpack2(dpp1, da, db);
            float att1 = (da + db) / fmaxf(sqrtf(sa + sb), EPS);
            ob[base + tid]       = att0;      // coalesced direct store
            ob[base + tid + 128] = att1;
            lsum += __expf(att0 - 1.0f) + __expf(att1 - 1.0f);
        }
        __syncthreads();
    }

    // ---- block reduce exp-sum -> g_partial ----
    #pragma unroll
    for (int o = 16; o; o >>= 1)
        lsum += __shfl_xor_sync(0xFFFFFFFFu, lsum, o);
    if ((tid & 31) == 0) s_red[tid >> 5] = lsum;
    __syncthreads();
    if (tid == 0)
        g_partial[b * NC + c] = s_red[0] + s_red[1] + s_red[2] + s_red[3];
}

// Kernel 2: per batch row, combine NC partials -> lse, subtract (float4 sweep).
__global__ __launch_bounds__(256) void attn_cosine_pass2(
    float* __restrict__ out, int S)
{
    __shared__ float s_lse;
    const int b   = blockIdx.x;
    const int tid = threadIdx.x;

    if (tid == 0) {
        float s = 0.f;
        #pragma unroll
        for (int c = 0; c < NC; c++) s += g_partial[b * NC + c];
        s_lse = 1.0f + logf(s);
    }
    __syncthreads();
    const float lse = s_lse;

    float4* o4 = reinterpret_cast<float4*>(out + (size_t)b * S);
    const int n4 = S / 4;
    #pragma unroll
    for (int i = tid; i < n4; i += 256) {
        float4 v = o4[i];
        v.x -= lse; v.y -= lse; v.z -= lse; v.w -= lse;
        o4[i] = v;
    }
}

extern "C" void kernel_launch(void* const* d_in, const int* in_sizes, int n_in,
                              void* d_out, int out_size) {
    const float* dec = (const float*)d_in[0];   // [B,32]
    const float* enc = (const float*)d_in[1];   // [B,S,32]
    const float* Wq  = (const float*)d_in[2];   // [16,32]
    const float* bq  = (const float*)d_in[3];   // [16]
    const float* Wk  = (const float*)d_in[4];   // [16,32]
    const float* bk  = (const float*)d_in[5];   // [16]
    float* out = (float*)d_out;

    const int H = 32;
    const int B = in_sizes[0] / H;                 // 512
    const int S = in_sizes[1] / (B * H);           // 4096

    cudaFuncSetAttribute(attn_cosine_pass1,
                         cudaFuncAttributeMaxDynamicSharedMemorySize, SMEM_BYTES);
    attn_cosine_pass1<<<B * NC, THREADS, SMEM_BYTES>>>(dec, enc, Wq, bq, Wk, bk, out, S);
    attn_cosine_pass2<<<B, 256>>>(out, S);
}